// round 1
// baseline (speedup 1.0000x reference)
#include <cuda_runtime.h>
#include <cstdint>

// ACoef: per-sample traces of x^2..x^11 for 65536 16x16 fp32 matrices,
// then out[b] = sum_{i,j} coef[i][j] * tr_{i+2}^{j+1} / 256^{i+j+1}.
//
// Addition-chain: compute X2=X*X, X3=X*X2, X5=X2*X3, X6=X3*X3 (4 matmuls).
// Traces: tr2,tr3 = diagonals; tr4=<X2,X2^T>, tr5=<X3,X2^T>, tr6=<X3,X3^T>,
// tr7=<X5,X2^T>, tr8=<X5,X3^T>, tr9=<X6,X3^T>, tr10=<X5,X5^T>, tr11=<X6,X5^T>.
//
// One half-warp (16 lanes) per sample; each lane owns a 4x4 output block.
// Matmuls use packed fp32x2 FMA (fma.rn.f32x2) vectorized along K:
// A stored row-major, B stored transposed, so both 64-bit operand pairs come
// directly from ld.shared.v2.b64 (no splats).

#define NSAMP 4            // samples per CTA (64 threads, 2 warps)
#define SAMP_STRIDE 272    // floats per sample region: 1088B == 64 mod 128 -> the
                           // two samples of a warp hit complementary smem banks
#define NBUF 7
enum { BX = 0, BXT, BX2, BX2T, BX3, BX3T, BX5 };

__device__ __forceinline__ unsigned long long f2fma(unsigned long long a,
                                                    unsigned long long b,
                                                    unsigned long long c) {
    unsigned long long d;
    asm("fma.rn.f32x2 %0, %1, %2, %3;" : "=l"(d) : "l"(a), "l"(b), "l"(c));
    return d;
}
__device__ __forceinline__ void f2unpack(unsigned long long v, float& lo, float& hi) {
    asm("mov.b64 {%0, %1}, %2;" : "=f"(lo), "=f"(hi) : "l"(v));
}
__device__ __forceinline__ void lds_v2b64(uint32_t addr, unsigned long long& lo,
                                          unsigned long long& hi) {
    asm volatile("ld.shared.v2.b64 {%0, %1}, [%2];" : "=l"(lo), "=l"(hi) : "r"(addr));
}
__device__ __forceinline__ float4 lds_v4f32(uint32_t addr) {
    float4 v;
    asm volatile("ld.shared.v4.f32 {%0,%1,%2,%3}, [%4];"
                 : "=f"(v.x), "=f"(v.y), "=f"(v.z), "=f"(v.w) : "r"(addr));
    return v;
}
__device__ __forceinline__ void sts_v4f32(uint32_t addr, float a, float b, float c, float d) {
    asm volatile("st.shared.v4.f32 [%0], {%1,%2,%3,%4};"
                 :: "r"(addr), "f"(a), "f"(b), "f"(c), "f"(d));
}
__device__ __forceinline__ void sts_f32(uint32_t addr, float a) {
    asm volatile("st.shared.f32 [%0], %1;" :: "r"(addr), "f"(a));
}

// C_block[4][4] = (A * B)(r0..r0+3, c0..c0+3); A at Abase row-major (16 floats/row),
// B^T at BTbase row-major. Packed-K fp32x2 FMA; horizontal add at the end.
__device__ __forceinline__ void mm16(uint32_t Abase, uint32_t BTbase, int r0, int c0,
                                     float blk[4][4]) {
    unsigned long long acc[4][4];
#pragma unroll
    for (int i = 0; i < 4; i++)
#pragma unroll
        for (int j = 0; j < 4; j++) acc[i][j] = 0ull;

#pragma unroll
    for (int kb = 0; kb < 4; kb++) {
        unsigned long long alo[4], ahi[4], blo[4], bhi[4];
#pragma unroll
        for (int i = 0; i < 4; i++)
            lds_v2b64(Abase + ((r0 + i) * 16 + kb * 4) * 4, alo[i], ahi[i]);
#pragma unroll
        for (int j = 0; j < 4; j++)
            lds_v2b64(BTbase + ((c0 + j) * 16 + kb * 4) * 4, blo[j], bhi[j]);
#pragma unroll
        for (int i = 0; i < 4; i++)
#pragma unroll
            for (int j = 0; j < 4; j++) {
                acc[i][j] = f2fma(alo[i], blo[j], acc[i][j]);
                acc[i][j] = f2fma(ahi[i], bhi[j], acc[i][j]);
            }
    }
#pragma unroll
    for (int i = 0; i < 4; i++)
#pragma unroll
        for (int j = 0; j < 4; j++) {
            float lo, hi;
            f2unpack(acc[i][j], lo, hi);
            blk[i][j] = lo + hi;
        }
}

__device__ __forceinline__ void store_blk(uint32_t base, int r0, int c0, const float blk[4][4]) {
#pragma unroll
    for (int i = 0; i < 4; i++)
        sts_v4f32(base + ((r0 + i) * 16 + c0) * 4, blk[i][0], blk[i][1], blk[i][2], blk[i][3]);
}
__device__ __forceinline__ void store_blkT(uint32_t base, int r0, int c0, const float blk[4][4]) {
#pragma unroll
    for (int j = 0; j < 4; j++)
        sts_v4f32(base + ((c0 + j) * 16 + r0) * 4, blk[0][j], blk[1][j], blk[2][j], blk[3][j]);
}

// sum_{i,j} blk[i][j] * T[r0+i][c0+j]   (T is a transposed-layout buffer)
__device__ __forceinline__ float trace_dotT(uint32_t Tbase, int r0, int c0, const float blk[4][4]) {
    float t = 0.f;
#pragma unroll
    for (int i = 0; i < 4; i++) {
        float4 v = lds_v4f32(Tbase + ((r0 + i) * 16 + c0) * 4);
        t += blk[i][0] * v.x + blk[i][1] * v.y + blk[i][2] * v.z + blk[i][3] * v.w;
    }
    return t;
}
// sum_{i,j} blk[i][j] * M[c0+j][r0+i]   (M is a normal-layout buffer)
__device__ __forceinline__ float trace_dotN(uint32_t Mbase, int r0, int c0, const float blk[4][4]) {
    float t = 0.f;
#pragma unroll
    for (int j = 0; j < 4; j++) {
        float4 v = lds_v4f32(Mbase + ((c0 + j) * 16 + r0) * 4);
        t += blk[0][j] * v.x + blk[1][j] * v.y + blk[2][j] * v.z + blk[3][j] * v.w;
    }
    return t;
}

__global__ void __launch_bounds__(64)
acoef_kernel(const float* __restrict__ x, const float* __restrict__ coef,
             float* __restrict__ out, int nsamples) {
    __shared__ float smem[NBUF * NSAMP * SAMP_STRIDE];
    uint32_t sbase = (uint32_t)__cvta_generic_to_shared(smem);

    const int tid  = threadIdx.x;
    const int lane = tid & 31;
    const int half = lane >> 4;
    const int s    = (tid >> 5) * 2 + half;   // local sample 0..3
    const int ln   = lane & 15;
    const int br   = ln >> 2, bc = ln & 3;
    const int r0   = br * 4, c0 = bc * 4;

    const long gsample = (long)blockIdx.x * NSAMP + s;
    if (gsample >= nsamples) return;
    const float* gx = x + gsample * 256;

    uint32_t base[NBUF];
#pragma unroll
    for (int b = 0; b < NBUF; b++)
        base[b] = sbase + (uint32_t)((b * NSAMP + s) * SAMP_STRIDE) * 4u;

    // ---- load X (lane ln owns row ln), store X and X^T ----
    float4 row4[4];
#pragma unroll
    for (int j = 0; j < 4; j++)
        row4[j] = __ldg((const float4*)(gx + ln * 16 + j * 4));
#pragma unroll
    for (int j = 0; j < 4; j++)
        sts_v4f32(base[BX] + (ln * 16 + j * 4) * 4, row4[j].x, row4[j].y, row4[j].z, row4[j].w);
    {
        const float* rp = (const float*)row4;
#pragma unroll
        for (int k = 0; k < 16; k++)
            sts_f32(base[BXT] + (k * 16 + ln) * 4, rp[k]);
    }
    __syncwarp();

    float tr[10];
    float blk[4][4];
    float d;

    // ---- mm1: X2 = X * X ----
    mm16(base[BX], base[BXT], r0, c0, blk);
    d = 0.f;
    if (br == bc) {
#pragma unroll
        for (int i = 0; i < 4; i++) d += blk[i][i];
    }
    tr[0] = d;                                          // tr(x^2)
    store_blk(base[BX2], r0, c0, blk);
    store_blkT(base[BX2T], r0, c0, blk);
    __syncwarp();
    tr[2] = trace_dotT(base[BX2T], r0, c0, blk);        // tr(x^4)

    // ---- mm2: X3 = X * X2 ----
    mm16(base[BX], base[BX2T], r0, c0, blk);
    d = 0.f;
    if (br == bc) {
#pragma unroll
        for (int i = 0; i < 4; i++) d += blk[i][i];
    }
    tr[1] = d;                                          // tr(x^3)
    tr[3] = trace_dotT(base[BX2T], r0, c0, blk);        // tr(x^5)
    store_blk(base[BX3], r0, c0, blk);
    store_blkT(base[BX3T], r0, c0, blk);
    __syncwarp();
    tr[4] = trace_dotT(base[BX3T], r0, c0, blk);        // tr(x^6)

    // ---- mm3: X5 = X2 * X3 ----
    mm16(base[BX2], base[BX3T], r0, c0, blk);
    tr[5] = trace_dotT(base[BX2T], r0, c0, blk);        // tr(x^7)
    tr[6] = trace_dotT(base[BX3T], r0, c0, blk);        // tr(x^8)
    store_blk(base[BX5], r0, c0, blk);
    __syncwarp();
    tr[8] = trace_dotN(base[BX5], r0, c0, blk);         // tr(x^10)

    // ---- mm4: X6 = X3 * X3 (registers only) ----
    mm16(base[BX3], base[BX3T], r0, c0, blk);
    tr[7] = trace_dotT(base[BX3T], r0, c0, blk);        // tr(x^9)
    tr[9] = trace_dotN(base[BX5], r0, c0, blk);         // tr(x^11)

    // ---- reduce traces across the 16 lanes of this half-warp ----
#pragma unroll
    for (int i = 0; i < 10; i++) {
#pragma unroll
        for (int off = 8; off >= 1; off >>= 1)
            tr[i] += __shfl_xor_sync(0xffffffffu, tr[i], off);
    }

    // ---- final polynomial: out = sum coef[i][j] * (tr_i/256)^(j+1) / 256^i ----
    if (ln == 0) {
        const float inv256 = 1.0f / 256.0f;
        float res  = 0.f;
        float invp = 1.f;
#pragma unroll
        for (int i = 0; i < 10; i++) {
            float u  = tr[i] * inv256;
            float up = u;
            float a  = 0.f;
#pragma unroll
            for (int j = 0; j < 4; j++) {
                a += coef[i * 4 + j] * up;
                up *= u;
            }
            res += a * invp;
            invp *= inv256;
        }
        out[gsample] = res;
    }
}

extern "C" void kernel_launch(void* const* d_in, const int* in_sizes, int n_in,
                              void* d_out, int out_size) {
    const float* x;
    const float* coef;
    if (n_in >= 2 && in_sizes[0] == 40) {  // coef first if sizes say so
        coef = (const float*)d_in[0];
        x    = (const float*)d_in[1];
    } else {
        x    = (const float*)d_in[0];
        coef = (const float*)d_in[1];
    }
    float* out = (float*)d_out;
    int nsamples = out_size;
    int grid = (nsamples + NSAMP - 1) / NSAMP;
    acoef_kernel<<<grid, 64>>>(x, coef, out, nsamples);
}

// round 2
// speedup vs baseline: 2.3091x; 2.3091x over previous
#include <cuda_runtime.h>
#include <cstdint>

// ACoef: per-sample traces of x^2..x^11 for 65536 16x16 fp32 matrices,
// then out[b] = sum_{i,j} coef[i][j] * tr_{i+2}^(j+1) / 256^(i+j+1).
//
// Addition chain: X2=X*X, X3=X*X2, X5=X2*X3, X6=X3*X3 (4 matmuls).
// tr2,tr3 from diagonals; tr4=<X2,X2^T>, tr5=<X3,X2^T>, tr6=<X3,X3^T>,
// tr7=<X5,X2^T>, tr8=<X5,X3^T>, tr9=<X6,X3^T>, tr10=<X5,X5^T>, tr11=<X6,X5^T>.
//
// One half-warp per sample; lane owns a 4x4 output block (g=row-group, h=col-group).
// Matmuls: packed fp32x2 FMA along K; A row-major, B stored transposed so both
// 64-bit operand pairs come from ld.shared.v2.b64.
//
// R2 changes vs R1:
//  - XOR chunk swizzle (chunk ^= row>>2) -> mm loads conflict-free (1 phase, was 4)
//  - 5 smem slots with liveness reuse (X3 -> XT slot, X5 -> X slot): 21.8KB/block
//  - mm restructured for fewer live regs + __launch_bounds__(64,10)

#define NSAMP 4            // samples per CTA (64 threads, 2 warps)
#define MATSTRIDE 272      // floats per matrix slot: 1088B == 64 mod 128 ->
                           // the two samples of a warp hit complementary halves
#define NSLOT 5

__device__ __forceinline__ unsigned long long f2fma(unsigned long long a,
                                                    unsigned long long b,
                                                    unsigned long long c) {
    unsigned long long d;
    asm("fma.rn.f32x2 %0, %1, %2, %3;" : "=l"(d) : "l"(a), "l"(b), "l"(c));
    return d;
}
__device__ __forceinline__ void f2unpack(unsigned long long v, float& lo, float& hi) {
    asm("mov.b64 {%0, %1}, %2;" : "=f"(lo), "=f"(hi) : "l"(v));
}
__device__ __forceinline__ void lds_v2b64(uint32_t addr, unsigned long long& lo,
                                          unsigned long long& hi) {
    asm volatile("ld.shared.v2.b64 {%0, %1}, [%2];" : "=l"(lo), "=l"(hi) : "r"(addr));
}
__device__ __forceinline__ float4 lds_v4f32(uint32_t addr) {
    float4 v;
    asm volatile("ld.shared.v4.f32 {%0,%1,%2,%3}, [%4];"
                 : "=f"(v.x), "=f"(v.y), "=f"(v.z), "=f"(v.w) : "r"(addr));
    return v;
}
__device__ __forceinline__ void sts_v4f32(uint32_t addr, float a, float b, float c, float d) {
    asm volatile("st.shared.v4.f32 [%0], {%1,%2,%3,%4};"
                 :: "r"(addr), "f"(a), "f"(b), "f"(c), "f"(d));
}
__device__ __forceinline__ void sts_f32(uint32_t addr, float a) {
    asm volatile("st.shared.f32 [%0], %1;" :: "r"(addr), "f"(a));
}

// Swizzled float-index of (row, 16B-chunk): chunk stored at chunk ^ (row>>2).
__device__ __forceinline__ uint32_t swz_addr(uint32_t base, int row, int chunk) {
    return base + (uint32_t)(row * 16 + ((chunk ^ (row >> 2)) & 3) * 4) * 4u;
}

// C_block(g,h) of A*B; A row-major at Abase, B^T row-major at BTbase (swizzled).
__device__ __forceinline__ void mm16(uint32_t Abase, uint32_t BTbase, int g, int h,
                                     float blk[4][4]) {
    unsigned long long acc[4][4];
#pragma unroll
    for (int i = 0; i < 4; i++)
#pragma unroll
        for (int j = 0; j < 4; j++) acc[i][j] = 0ull;

#pragma unroll
    for (int kb = 0; kb < 4; kb++) {
        unsigned long long alo[4], ahi[4];
#pragma unroll
        for (int i = 0; i < 4; i++)
            lds_v2b64(swz_addr(Abase, 4 * g + i, kb), alo[i], ahi[i]);
#pragma unroll
        for (int j = 0; j < 4; j++) {
            unsigned long long blo, bhi;
            lds_v2b64(swz_addr(BTbase, 4 * h + j, kb), blo, bhi);
#pragma unroll
            for (int i = 0; i < 4; i++) {
                acc[i][j] = f2fma(alo[i], blo, acc[i][j]);
                acc[i][j] = f2fma(ahi[i], bhi, acc[i][j]);
            }
        }
    }
#pragma unroll
    for (int i = 0; i < 4; i++)
#pragma unroll
        for (int j = 0; j < 4; j++) {
            float lo, hi;
            f2unpack(acc[i][j], lo, hi);
            blk[i][j] = lo + hi;
        }
}

// store block normal-layout: rows 4g+i, chunk h^g after swizzle
__device__ __forceinline__ void store_blk(uint32_t base, int g, int h, const float blk[4][4]) {
#pragma unroll
    for (int i = 0; i < 4; i++)
        sts_v4f32(swz_addr(base, 4 * g + i, h), blk[i][0], blk[i][1], blk[i][2], blk[i][3]);
}
// store block transposed-layout: rows 4h+j, chunk g
__device__ __forceinline__ void store_blkT(uint32_t base, int g, int h, const float blk[4][4]) {
#pragma unroll
    for (int j = 0; j < 4; j++)
        sts_v4f32(swz_addr(base, 4 * h + j, g), blk[0][j], blk[1][j], blk[2][j], blk[3][j]);
}

// sum_{i,j} blk[i][j] * T[4g+i][4h+j]  (T is a transposed-layout buffer)
__device__ __forceinline__ float trace_dotT(uint32_t Tbase, int g, int h, const float blk[4][4]) {
    float t = 0.f;
#pragma unroll
    for (int i = 0; i < 4; i++) {
        float4 v = lds_v4f32(swz_addr(Tbase, 4 * g + i, h));
        t += blk[i][0] * v.x + blk[i][1] * v.y + blk[i][2] * v.z + blk[i][3] * v.w;
    }
    return t;
}
// sum_{i,j} blk[i][j] * M[4h+j][4g+i]  (M is a normal-layout buffer)
__device__ __forceinline__ float trace_dotN(uint32_t Mbase, int g, int h, const float blk[4][4]) {
    float t = 0.f;
#pragma unroll
    for (int j = 0; j < 4; j++) {
        float4 v = lds_v4f32(swz_addr(Mbase, 4 * h + j, g));
        t += blk[0][j] * v.x + blk[1][j] * v.y + blk[2][j] * v.z + blk[3][j] * v.w;
    }
    return t;
}

__global__ void __launch_bounds__(64, 10)
acoef_kernel(const float* __restrict__ x, const float* __restrict__ coef,
             float* __restrict__ out, int nsamples) {
    __shared__ float smem[NSLOT * NSAMP * MATSTRIDE];
    uint32_t sbase = (uint32_t)__cvta_generic_to_shared(smem);

    const int tid  = threadIdx.x;
    const int lane = tid & 31;
    const int half = lane >> 4;
    const int s    = (tid >> 5) * 2 + half;   // local sample 0..3
    const int ln   = lane & 15;
    const int g    = ln >> 2;                 // block-row group
    const int h    = ln & 3;                  // block-col group

    const long gsample = (long)blockIdx.x * NSAMP + s;
    if (gsample >= nsamples) return;
    const float* gx = x + gsample * 256;

    // slot bases (per-sample regions)
    uint32_t slot[NSLOT];
#pragma unroll
    for (int b = 0; b < NSLOT; b++)
        slot[b] = sbase + (uint32_t)((b * NSAMP + s) * MATSTRIDE) * 4u;

    // liveness-reused slot assignment
    const uint32_t BX   = slot[0];  // X, later X5
    const uint32_t BXT  = slot[1];  // X^T, later X3
    const uint32_t BX2  = slot[2];
    const uint32_t BX2T = slot[3];
    const uint32_t BX3T = slot[4];
    const uint32_t BX3  = BXT;      // alias after XT dies
    const uint32_t BX5  = BX;       // alias after X dies

    // ---- load X (lane ln owns row ln); store X (swizzled) and X^T ----
    float4 row4[4];
#pragma unroll
    for (int j = 0; j < 4; j++)
        row4[j] = __ldg((const float4*)(gx + ln * 16 + j * 4));
#pragma unroll
    for (int j = 0; j < 4; j++)
        sts_v4f32(swz_addr(BX, ln, j), row4[j].x, row4[j].y, row4[j].z, row4[j].w);
    {
        const float* rp = (const float*)row4;
#pragma unroll
        for (int k = 0; k < 16; k++) {
            // X^T element (k, ln): row k, chunk ln>>2, within-chunk ln&3
            uint32_t a = swz_addr(BXT, k, ln >> 2) + (uint32_t)(ln & 3) * 4u;
            sts_f32(a, rp[k]);
        }
    }
    __syncwarp();

    float tr[10];
    float blk[4][4];
    float d;

    // ---- mm1: X2 = X * X ----
    mm16(BX, BXT, g, h, blk);
    d = 0.f;
    if (g == h) {
#pragma unroll
        for (int i = 0; i < 4; i++) d += blk[i][i];
    }
    tr[0] = d;                                  // tr(x^2)
    store_blk(BX2, g, h, blk);
    store_blkT(BX2T, g, h, blk);
    __syncwarp();
    tr[2] = trace_dotT(BX2T, g, h, blk);        // tr(x^4)

    // ---- mm2: X3 = X * X2 ----  (XT dead after mm1 -> X3 goes to its slot)
    mm16(BX, BX2T, g, h, blk);
    d = 0.f;
    if (g == h) {
#pragma unroll
        for (int i = 0; i < 4; i++) d += blk[i][i];
    }
    tr[1] = d;                                  // tr(x^3)
    tr[3] = trace_dotT(BX2T, g, h, blk);        // tr(x^5)
    store_blk(BX3, g, h, blk);
    store_blkT(BX3T, g, h, blk);
    __syncwarp();                               // also: all X reads done before X5 store
    tr[4] = trace_dotT(BX3T, g, h, blk);        // tr(x^6)

    // ---- mm3: X5 = X2 * X3 ----  (X dead -> X5 goes to its slot)
    mm16(BX2, BX3T, g, h, blk);
    tr[5] = trace_dotT(BX2T, g, h, blk);        // tr(x^7)
    tr[6] = trace_dotT(BX3T, g, h, blk);        // tr(x^8)
    store_blk(BX5, g, h, blk);
    __syncwarp();
    tr[8] = trace_dotN(BX5, g, h, blk);         // tr(x^10)

    // ---- mm4: X6 = X3 * X3 (block stays in registers) ----
    mm16(BX3, BX3T, g, h, blk);
    tr[7] = trace_dotT(BX3T, g, h, blk);        // tr(x^9)
    tr[9] = trace_dotN(BX5, g, h, blk);         // tr(x^11)

    // ---- reduce traces across the 16 lanes of this half-warp ----
#pragma unroll
    for (int i = 0; i < 10; i++) {
#pragma unroll
        for (int off = 8; off >= 1; off >>= 1)
            tr[i] += __shfl_xor_sync(0xffffffffu, tr[i], off);
    }

    // ---- out = sum coef[i][j] * (tr_i/256)^(j+1) / 256^i ----
    if (ln == 0) {
        const float inv256 = 1.0f / 256.0f;
        float res  = 0.f;
        float invp = 1.f;
#pragma unroll
        for (int i = 0; i < 10; i++) {
            float u  = tr[i] * inv256;
            float up = u;
            float a  = 0.f;
#pragma unroll
            for (int j = 0; j < 4; j++) {
                a += __ldg(coef + i * 4 + j) * up;
                up *= u;
            }
            res += a * invp;
            invp *= inv256;
        }
        out[gsample] = res;
    }
}

extern "C" void kernel_launch(void* const* d_in, const int* in_sizes, int n_in,
                              void* d_out, int out_size) {
    const float* x;
    const float* coef;
    if (n_in >= 2 && in_sizes[0] == 40) {  // coef first if sizes say so
        coef = (const float*)d_in[0];
        x    = (const float*)d_in[1];
    } else {
        x    = (const float*)d_in[0];
        coef = (const float*)d_in[1];
    }
    float* out = (float*)d_out;
    int nsamples = out_size;
    int grid = (nsamples + NSAMP - 1) / NSAMP;
    acoef_kernel<<<grid, 64>>>(x, coef, out, nsamples);
}

// round 3
// speedup vs baseline: 2.9641x; 1.2837x over previous
#include <cuda_runtime.h>
#include <cstdint>

// ACoef: per-sample traces of x^2..x^11 for 65536 16x16 fp32 matrices,
// out[b] = sum_{i,j} coef[i][j] * tr_{i+2}^(j+1) / 256^(i+j+1).
//
// One sample per WARP. All matmuls on tensor cores via mma.sync m16n8k8
// tf32 with 3xTF32 error compensation (AhiBhi + AhiBlo + AloBhi).
// Chain: x2=X*X, x3=X*x2, x4=X*x3, x5=X*x4, x6=X*x5 (A-operand = X, fixed
// register fragments). tr2..tr6 = diagonals (free). tr7..tr11 via register
// transposes of x4,x5 and elementwise fragment dots. Zero shared memory.

// ---------- small helpers ----------
__device__ __forceinline__ uint32_t f2tf32(float v) {
    uint32_t r;
    asm("cvt.rna.tf32.f32 %0, %1;" : "=r"(r) : "f"(v));
    return r;
}
__device__ __forceinline__ void split_tf32(float v, uint32_t& hi, uint32_t& lo) {
    hi = f2tf32(v);
    float hif = __uint_as_float(hi);
    lo = f2tf32(v - hif);
}
__device__ __forceinline__ void mma_tf32(float d[4], const uint32_t a[4],
                                         const uint32_t b[2], const float c[4]) {
    asm volatile(
        "mma.sync.aligned.m16n8k8.row.col.f32.tf32.tf32.f32 "
        "{%0,%1,%2,%3}, {%4,%5,%6,%7}, {%8,%9}, {%10,%11,%12,%13};"
        : "=f"(d[0]), "=f"(d[1]), "=f"(d[2]), "=f"(d[3])
        : "r"(a[0]), "r"(a[1]), "r"(a[2]), "r"(a[3]),
          "r"(b[0]), "r"(b[1]),
          "f"(c[0]), "f"(c[1]), "f"(c[2]), "f"(c[3]));
}
__device__ __forceinline__ float shfl(float v, int src) {
    return __shfl_sync(0xffffffffu, v, src);
}

// C-fragment of a 16x16 fp32 matrix: CH[nn][4], nn = n-half (cols 8nn..8nn+7).
// Lane (g = lane>>2, t = lane&3):
//   CH[nn][0] = M[g  ][8nn+2t]   CH[nn][1] = M[g  ][8nn+2t+1]
//   CH[nn][2] = M[g+8][8nn+2t]   CH[nn][3] = M[g+8][8nn+2t+1]
// Element M[R][C] lives in lane (R&7)*4 + ((C&7)>>1), reg CH[C>>3][2*(R>>3)+(C&1)].

// Convert C-frag -> col-major B-frags with tf32 hi/lo split.
// B-frag (kk,nn): b0 = M[8kk+t][8nn+g], b1 = M[8kk+t+4][8nn+g].
__device__ __forceinline__ void conv_to_B(const float CH[2][4], int g, int t,
                                          uint32_t Bhi[2][2][2], uint32_t Blo[2][2][2]) {
    const int L  = 4 * t + (g >> 1);
    const int L2 = L + 16;
    const bool odd = (g & 1);
#pragma unroll
    for (int nn = 0; nn < 2; nn++)
#pragma unroll
        for (int kk = 0; kk < 2; kk++) {
            float e  = shfl(CH[nn][2 * kk],     L);
            float o  = shfl(CH[nn][2 * kk + 1], L);
            float b0 = odd ? o : e;
            float e2 = shfl(CH[nn][2 * kk],     L2);
            float o2 = shfl(CH[nn][2 * kk + 1], L2);
            float b1 = odd ? o2 : e2;
            split_tf32(b0, Bhi[kk][nn][0], Blo[kk][nn][0]);
            split_tf32(b1, Bhi[kk][nn][1], Blo[kk][nn][1]);
        }
}

// Register transpose: TH = C-frag layout of M^T given CH of M.
// Target TH[nn][r]: positions (g(+8), 8nn+2t(+1)) of M^T = M[8nn+2t(+1)][g(+8)].
__device__ __forceinline__ void transpose_frag(const float CH[2][4], int g, int t,
                                               float TH[2][4]) {
    const int l0 = 8 * t + (g >> 1);
    const int l1 = l0 + 4;
    const bool odd = (g & 1);
#pragma unroll
    for (int nn = 0; nn < 2; nn++) {
        float e00 = shfl(CH[0][2 * nn],     l0);
        float o00 = shfl(CH[0][2 * nn + 1], l0);
        TH[nn][0] = odd ? o00 : e00;                 // M[8nn+2t][g]
        float e10 = shfl(CH[1][2 * nn],     l0);
        float o10 = shfl(CH[1][2 * nn + 1], l0);
        TH[nn][2] = odd ? o10 : e10;                 // M[8nn+2t][g+8]
        float e01 = shfl(CH[0][2 * nn],     l1);
        float o01 = shfl(CH[0][2 * nn + 1], l1);
        TH[nn][1] = odd ? o01 : e01;                 // M[8nn+2t+1][g]
        float e11 = shfl(CH[1][2 * nn],     l1);
        float o11 = shfl(CH[1][2 * nn + 1], l1);
        TH[nn][3] = odd ? o11 : e11;                 // M[8nn+2t+1][g+8]
    }
}

// Per-lane partial of trace(M) from its C-frag.
__device__ __forceinline__ float diag_partial(const float CH[2][4], int g, int t) {
    float s = 0.f;
#pragma unroll
    for (int nn = 0; nn < 2; nn++)
#pragma unroll
        for (int r = 0; r < 4; r++) {
            int rr = g + 8 * (r >> 1);
            int cc = 8 * nn + 2 * t + (r & 1);
            if (rr == cc) s += CH[nn][r];
        }
    return s;
}

// Per-lane partial of sum(A .* B) over fragment positions.
__device__ __forceinline__ float frag_dot(const float A[2][4], const float B[2][4]) {
    float s = 0.f;
#pragma unroll
    for (int nn = 0; nn < 2; nn++)
#pragma unroll
        for (int r = 0; r < 4; r++) s = fmaf(A[nn][r], B[nn][r], s);
    return s;
}

// D = X * P (3xTF32), X given as Ahi/Alo frags, P as Bhi/Blo frags.
__device__ __forceinline__ void mm_chain(const uint32_t Ahi[2][4], const uint32_t Alo[2][4],
                                         const uint32_t Bhi[2][2][2], const uint32_t Blo[2][2][2],
                                         float D[2][4]) {
#pragma unroll
    for (int nn = 0; nn < 2; nn++) {
        float d[4] = {0.f, 0.f, 0.f, 0.f};
#pragma unroll
        for (int kk = 0; kk < 2; kk++) {
            mma_tf32(d, Ahi[kk], Blo[kk][nn], d);
            mma_tf32(d, Alo[kk], Bhi[kk][nn], d);
            mma_tf32(d, Ahi[kk], Bhi[kk][nn], d);
        }
#pragma unroll
        for (int r = 0; r < 4; r++) D[nn][r] = d[r];
    }
}

__global__ void __launch_bounds__(128)
acoef_kernel(const float* __restrict__ x, const float* __restrict__ coef,
             float* __restrict__ out, int nsamples) {
    const int lane = threadIdx.x & 31;
    const int g = lane >> 2;   // groupID (row within 8)
    const int t = lane & 3;    // thread-in-group (col within 4)

    const long sample = (long)blockIdx.x * (blockDim.x >> 5) + (threadIdx.x >> 5);
    if (sample >= nsamples) return;
    const float* gx = x + sample * 256;

    // ---- load X fragments ----
    // A (row-major m16k8) frags per k-half kk:
    //   a0=(g,8kk+t) a1=(g+8,8kk+t) a2=(g,8kk+t+4) a3=(g+8,8kk+t+4)
    uint32_t Ahi[2][4], Alo[2][4];
#pragma unroll
    for (int kk = 0; kk < 2; kk++) {
#pragma unroll
        for (int idx = 0; idx < 4; idx++) {
            int row = g + 8 * (idx & 1);
            int col = 8 * kk + t + 4 * (idx >> 1);
            float v = __ldg(gx + row * 16 + col);
            split_tf32(v, Ahi[kk][idx], Alo[kk][idx]);
        }
    }
    // B of X (for mm1): b0 = X[8kk+t][8nn+g], b1 = X[8kk+t+4][8nn+g]
    uint32_t Bhi[2][2][2], Blo[2][2][2];
#pragma unroll
    for (int kk = 0; kk < 2; kk++)
#pragma unroll
        for (int nn = 0; nn < 2; nn++) {
            float b0 = __ldg(gx + (8 * kk + t) * 16 + 8 * nn + g);
            float b1 = __ldg(gx + (8 * kk + t + 4) * 16 + 8 * nn + g);
            split_tf32(b0, Bhi[kk][nn][0], Blo[kk][nn][0]);
            split_tf32(b1, Bhi[kk][nn][1], Blo[kk][nn][1]);
        }

    float tr[10];
    float C2[2][4], C3[2][4], C4[2][4], C5[2][4], C6[2][4];
    float T4[2][4], T5[2][4];

    // mm1: x2 = X*X
    mm_chain(Ahi, Alo, Bhi, Blo, C2);
    tr[0] = diag_partial(C2, g, t);                 // tr2

    // mm2: x3 = X*x2
    conv_to_B(C2, g, t, Bhi, Blo);
    mm_chain(Ahi, Alo, Bhi, Blo, C3);
    tr[1] = diag_partial(C3, g, t);                 // tr3

    // mm3: x4 = X*x3
    conv_to_B(C3, g, t, Bhi, Blo);
    mm_chain(Ahi, Alo, Bhi, Blo, C4);
    tr[2] = diag_partial(C4, g, t);                 // tr4

    transpose_frag(C4, g, t, T4);
    tr[5] = frag_dot(T4, C3);                       // tr7 = tr(x3*x4)
    tr[6] = frag_dot(T4, C4);                       // tr8 = tr(x4*x4)

    // mm4: x5 = X*x4
    conv_to_B(C4, g, t, Bhi, Blo);
    mm_chain(Ahi, Alo, Bhi, Blo, C5);
    tr[3] = diag_partial(C5, g, t);                 // tr5
    tr[7] = frag_dot(T4, C5);                       // tr9 = tr(x4*x5)

    transpose_frag(C5, g, t, T5);
    tr[8] = frag_dot(T5, C5);                       // tr10 = tr(x5*x5)

    // mm5: x6 = X*x5
    conv_to_B(C5, g, t, Bhi, Blo);
    mm_chain(Ahi, Alo, Bhi, Blo, C6);
    tr[4] = diag_partial(C6, g, t);                 // tr6
    tr[9] = frag_dot(T5, C6);                       // tr11 = tr(x5*x6)

    // ---- reduce partials over the 32 lanes ----
#pragma unroll
    for (int i = 0; i < 10; i++) {
#pragma unroll
        for (int off = 16; off >= 1; off >>= 1)
            tr[i] += __shfl_xor_sync(0xffffffffu, tr[i], off);
    }

    // ---- out = sum coef[i][j] * (tr_i/256)^(j+1) / 256^i ----
    if (lane == 0) {
        const float inv256 = 1.0f / 256.0f;
        float res = 0.f, invp = 1.f;
#pragma unroll
        for (int i = 0; i < 10; i++) {
            float u = tr[i] * inv256;
            float up = u, a = 0.f;
#pragma unroll
            for (int j = 0; j < 4; j++) {
                a += __ldg(coef + i * 4 + j) * up;
                up *= u;
            }
            res += a * invp;
            invp *= inv256;
        }
        out[sample] = res;
    }
}

extern "C" void kernel_launch(void* const* d_in, const int* in_sizes, int n_in,
                              void* d_out, int out_size) {
    const float* x;
    const float* coef;
    if (n_in >= 2 && in_sizes[0] == 40) {
        coef = (const float*)d_in[0];
        x    = (const float*)d_in[1];
    } else {
        x    = (const float*)d_in[0];
        coef = (const float*)d_in[1];
    }
    float* out = (float*)d_out;
    int nsamples = out_size;
    const int warps_per_cta = 4;
    int grid = (nsamples + warps_per_cta - 1) / warps_per_cta;
    acoef_kernel<<<grid, warps_per_cta * 32>>>(x, coef, out, nsamples);
}

// round 4
// speedup vs baseline: 3.3170x; 1.1190x over previous
#include <cuda_runtime.h>
#include <cstdint>

// ACoef: per-sample traces of x^2..x^11 for 65536 16x16 fp32 matrices,
// out[b] = sum_{i,j} coef[i][j] * tr_{i+2}^(j+1) / 256^(i+j+1).
//
// One sample per WARP, tensor-core mma m16n8k8 tf32 with 3xTF32 compensation.
// Chain x2..x6 with A = X fixed; cross traces via register transposes + dots.
// R4: recursive-halving reduce-scatter for the 10 traces (16 shfl, ends with
// trace i in lane 2i) + distributed polynomial epilogue (1 LDG.128/lane).

__device__ __forceinline__ uint32_t f2tf32(float v) {
    uint32_t r;
    asm("cvt.rna.tf32.f32 %0, %1;" : "=r"(r) : "f"(v));
    return r;
}
__device__ __forceinline__ void split_tf32(float v, uint32_t& hi, uint32_t& lo) {
    hi = f2tf32(v);
    float hif = __uint_as_float(hi);
    lo = f2tf32(v - hif);
}
__device__ __forceinline__ void mma_tf32(float d[4], const uint32_t a[4],
                                         const uint32_t b[2], const float c[4]) {
    asm volatile(
        "mma.sync.aligned.m16n8k8.row.col.f32.tf32.tf32.f32 "
        "{%0,%1,%2,%3}, {%4,%5,%6,%7}, {%8,%9}, {%10,%11,%12,%13};"
        : "=f"(d[0]), "=f"(d[1]), "=f"(d[2]), "=f"(d[3])
        : "r"(a[0]), "r"(a[1]), "r"(a[2]), "r"(a[3]),
          "r"(b[0]), "r"(b[1]),
          "f"(c[0]), "f"(c[1]), "f"(c[2]), "f"(c[3]));
}
__device__ __forceinline__ float shfl(float v, int src) {
    return __shfl_sync(0xffffffffu, v, src);
}

// C-fragment of a 16x16 fp32 matrix: CH[nn][4], nn = n-half (cols 8nn..8nn+7).
// Lane (g = lane>>2, t = lane&3):
//   CH[nn][0] = M[g  ][8nn+2t]   CH[nn][1] = M[g  ][8nn+2t+1]
//   CH[nn][2] = M[g+8][8nn+2t]   CH[nn][3] = M[g+8][8nn+2t+1]

// C-frag -> col-major B-frags with tf32 hi/lo split.
__device__ __forceinline__ void conv_to_B(const float CH[2][4], int g, int t,
                                          uint32_t Bhi[2][2][2], uint32_t Blo[2][2][2]) {
    const int L  = 4 * t + (g >> 1);
    const int L2 = L + 16;
    const bool odd = (g & 1);
#pragma unroll
    for (int nn = 0; nn < 2; nn++)
#pragma unroll
        for (int kk = 0; kk < 2; kk++) {
            float e  = shfl(CH[nn][2 * kk],     L);
            float o  = shfl(CH[nn][2 * kk + 1], L);
            float b0 = odd ? o : e;
            float e2 = shfl(CH[nn][2 * kk],     L2);
            float o2 = shfl(CH[nn][2 * kk + 1], L2);
            float b1 = odd ? o2 : e2;
            split_tf32(b0, Bhi[kk][nn][0], Blo[kk][nn][0]);
            split_tf32(b1, Bhi[kk][nn][1], Blo[kk][nn][1]);
        }
}

// Register transpose: TH = C-frag layout of M^T given CH of M.
__device__ __forceinline__ void transpose_frag(const float CH[2][4], int g, int t,
                                               float TH[2][4]) {
    const int l0 = 8 * t + (g >> 1);
    const int l1 = l0 + 4;
    const bool odd = (g & 1);
#pragma unroll
    for (int nn = 0; nn < 2; nn++) {
        float e00 = shfl(CH[0][2 * nn],     l0);
        float o00 = shfl(CH[0][2 * nn + 1], l0);
        TH[nn][0] = odd ? o00 : e00;
        float e10 = shfl(CH[1][2 * nn],     l0);
        float o10 = shfl(CH[1][2 * nn + 1], l0);
        TH[nn][2] = odd ? o10 : e10;
        float e01 = shfl(CH[0][2 * nn],     l1);
        float o01 = shfl(CH[0][2 * nn + 1], l1);
        TH[nn][1] = odd ? o01 : e01;
        float e11 = shfl(CH[1][2 * nn],     l1);
        float o11 = shfl(CH[1][2 * nn + 1], l1);
        TH[nn][3] = odd ? o11 : e11;
    }
}

__device__ __forceinline__ float diag_partial(const float CH[2][4], int g, int t) {
    float s = 0.f;
#pragma unroll
    for (int nn = 0; nn < 2; nn++)
#pragma unroll
        for (int r = 0; r < 4; r++) {
            int rr = g + 8 * (r >> 1);
            int cc = 8 * nn + 2 * t + (r & 1);
            if (rr == cc) s += CH[nn][r];
        }
    return s;
}

__device__ __forceinline__ float frag_dot(const float A[2][4], const float B[2][4]) {
    float s = 0.f;
#pragma unroll
    for (int nn = 0; nn < 2; nn++)
#pragma unroll
        for (int r = 0; r < 4; r++) s = fmaf(A[nn][r], B[nn][r], s);
    return s;
}

__device__ __forceinline__ void mm_chain(const uint32_t Ahi[2][4], const uint32_t Alo[2][4],
                                         const uint32_t Bhi[2][2][2], const uint32_t Blo[2][2][2],
                                         float D[2][4]) {
#pragma unroll
    for (int nn = 0; nn < 2; nn++) {
        float d[4] = {0.f, 0.f, 0.f, 0.f};
#pragma unroll
        for (int kk = 0; kk < 2; kk++) {
            mma_tf32(d, Ahi[kk], Blo[kk][nn], d);
            mma_tf32(d, Alo[kk], Bhi[kk][nn], d);
            mma_tf32(d, Ahi[kk], Bhi[kk][nn], d);
        }
#pragma unroll
        for (int r = 0; r < 4; r++) D[nn][r] = d[r];
    }
}

__global__ void __launch_bounds__(128)
acoef_kernel(const float* __restrict__ x, const float* __restrict__ coef,
             float* __restrict__ out, int nsamples) {
    const int lane = threadIdx.x & 31;
    const int g = lane >> 2;
    const int t = lane & 3;

    const long sample = (long)blockIdx.x * (blockDim.x >> 5) + (threadIdx.x >> 5);
    if (sample >= nsamples) return;
    const float* gx = x + sample * 256;

    // ---- load X fragments (A row-major, B col-major) with tf32 split ----
    uint32_t Ahi[2][4], Alo[2][4];
#pragma unroll
    for (int kk = 0; kk < 2; kk++) {
#pragma unroll
        for (int idx = 0; idx < 4; idx++) {
            int row = g + 8 * (idx & 1);
            int col = 8 * kk + t + 4 * (idx >> 1);
            float v = __ldg(gx + row * 16 + col);
            split_tf32(v, Ahi[kk][idx], Alo[kk][idx]);
        }
    }
    uint32_t Bhi[2][2][2], Blo[2][2][2];
#pragma unroll
    for (int kk = 0; kk < 2; kk++)
#pragma unroll
        for (int nn = 0; nn < 2; nn++) {
            float b0 = __ldg(gx + (8 * kk + t) * 16 + 8 * nn + g);
            float b1 = __ldg(gx + (8 * kk + t + 4) * 16 + 8 * nn + g);
            split_tf32(b0, Bhi[kk][nn][0], Blo[kk][nn][0]);
            split_tf32(b1, Bhi[kk][nn][1], Blo[kk][nn][1]);
        }

    float V[16];                    // trace partials; V[i] = tr(x^{i+2}), pad to 16
#pragma unroll
    for (int i = 10; i < 16; i++) V[i] = 0.f;

    float C2[2][4], C3[2][4], C4[2][4], C5[2][4], C6[2][4];
    float T4[2][4], T5[2][4];

    // mm1: x2 = X*X
    mm_chain(Ahi, Alo, Bhi, Blo, C2);
    V[0] = diag_partial(C2, g, t);                  // tr2

    // mm2: x3 = X*x2
    conv_to_B(C2, g, t, Bhi, Blo);
    mm_chain(Ahi, Alo, Bhi, Blo, C3);
    V[1] = diag_partial(C3, g, t);                  // tr3

    // mm3: x4 = X*x3
    conv_to_B(C3, g, t, Bhi, Blo);
    mm_chain(Ahi, Alo, Bhi, Blo, C4);
    V[2] = diag_partial(C4, g, t);                  // tr4

    transpose_frag(C4, g, t, T4);
    V[5] = frag_dot(T4, C3);                        // tr7 = tr(x3*x4)
    V[6] = frag_dot(T4, C4);                        // tr8 = tr(x4*x4)

    // mm4: x5 = X*x4
    conv_to_B(C4, g, t, Bhi, Blo);
    mm_chain(Ahi, Alo, Bhi, Blo, C5);
    V[3] = diag_partial(C5, g, t);                  // tr5
    V[7] = frag_dot(T4, C5);                        // tr9 = tr(x4*x5)

    transpose_frag(C5, g, t, T5);
    V[8] = frag_dot(T5, C5);                        // tr10 = tr(x5*x5)

    // mm5: x6 = X*x5
    conv_to_B(C5, g, t, Bhi, Blo);
    mm_chain(Ahi, Alo, Bhi, Blo, C6);
    V[4] = diag_partial(C6, g, t);                  // tr6
    V[9] = frag_dot(T5, C6);                        // tr11 = tr(x5*x6)

    // ---- recursive-halving reduce-scatter over 32 lanes ----
    // After: lane L holds the full sum of trace index (L>>1)&15.
    {
        const bool h16 = (lane & 16);
#pragma unroll
        for (int k = 0; k < 8; k++) {
            float send = h16 ? V[k] : V[k + 8];
            float recv = __shfl_xor_sync(0xffffffffu, send, 16);
            V[k] = (h16 ? V[k + 8] : V[k]) + recv;
        }
        const bool h8 = (lane & 8);
#pragma unroll
        for (int k = 0; k < 4; k++) {
            float send = h8 ? V[k] : V[k + 4];
            float recv = __shfl_xor_sync(0xffffffffu, send, 8);
            V[k] = (h8 ? V[k + 4] : V[k]) + recv;
        }
        const bool h4 = (lane & 4);
#pragma unroll
        for (int k = 0; k < 2; k++) {
            float send = h4 ? V[k] : V[k + 2];
            float recv = __shfl_xor_sync(0xffffffffu, send, 4);
            V[k] = (h4 ? V[k + 2] : V[k]) + recv;
        }
        {
            const bool h2 = (lane & 2);
            float send = h2 ? V[0] : V[1];
            float recv = __shfl_xor_sync(0xffffffffu, send, 2);
            V[0] = (h2 ? V[1] : V[0]) + recv;
        }
        V[0] += __shfl_xor_sync(0xffffffffu, V[0], 1);
    }

    // ---- distributed polynomial: lane with trace i computes row i ----
    {
        const int i = (lane >> 1) & 15;
        const bool active = (lane < 20) && ((lane & 1) == 0);
        const int ic = (i < 10) ? i : 0;
        const float4 cf = __ldg((const float4*)coef + ic);
        const float u  = V[0] * (1.0f / 256.0f);
        const float u2 = u * u;
        float term = cf.x * u + cf.y * u2 + cf.z * (u2 * u) + cf.w * (u2 * u2);
        term *= __uint_as_float((uint32_t)(127 - 8 * i) << 23);   // 256^{-i}
        term = active ? term : 0.f;
#pragma unroll
        for (int off = 16; off >= 1; off >>= 1)
            term += __shfl_xor_sync(0xffffffffu, term, off);
        if (lane == 0) out[sample] = term;
    }
}

extern "C" void kernel_launch(void* const* d_in, const int* in_sizes, int n_in,
                              void* d_out, int out_size) {
    const float* x;
    const float* coef;
    if (n_in >= 2 && in_sizes[0] == 40) {
        coef = (const float*)d_in[0];
        x    = (const float*)d_in[1];
    } else {
        x    = (const float*)d_in[0];
        coef = (const float*)d_in[1];
    }
    float* out = (float*)d_out;
    int nsamples = out_size;
    const int warps_per_cta = 4;
    int grid = (nsamples + warps_per_cta - 1) / warps_per_cta;
    acoef_kernel<<<grid, warps_per_cta * 32>>>(x, coef, out, nsamples);
}

// round 5
// speedup vs baseline: 4.1014x; 1.2365x over previous
#include <cuda_runtime.h>
#include <cstdint>

// ACoef: per-sample traces of x^2..x^11 for 65536 16x16 fp32 matrices,
// out[b] = sum_{i,j} coef[i][j] * tr_{i+2}^(j+1) / 256^(i+j+1).
//
// One sample per WARP, tensor-core mma m16n8k8 tf32 with 3xTF32 compensation.
// Chain x2..x6 with A = X fixed; cross traces via register transposes + dots.
// R5: (1) tf32 split via LOP3 mask + exact FADD (no cvt.rna chain);
//     (2) closed-form diagonal extraction (lane holds diag iff t == g>>1).

__device__ __forceinline__ void split_tf32(float v, uint32_t& hi, uint32_t& lo) {
    // hi = top 19 bits (tf32); lo = exact residual. mma ignores low 13 bits.
    hi = __float_as_uint(v) & 0xFFFFE000u;
    lo = __float_as_uint(v - __uint_as_float(hi));
}
__device__ __forceinline__ void mma_tf32(float d[4], const uint32_t a[4],
                                         const uint32_t b[2], const float c[4]) {
    asm volatile(
        "mma.sync.aligned.m16n8k8.row.col.f32.tf32.tf32.f32 "
        "{%0,%1,%2,%3}, {%4,%5,%6,%7}, {%8,%9}, {%10,%11,%12,%13};"
        : "=f"(d[0]), "=f"(d[1]), "=f"(d[2]), "=f"(d[3])
        : "r"(a[0]), "r"(a[1]), "r"(a[2]), "r"(a[3]),
          "r"(b[0]), "r"(b[1]),
          "f"(c[0]), "f"(c[1]), "f"(c[2]), "f"(c[3]));
}
__device__ __forceinline__ float shfl(float v, int src) {
    return __shfl_sync(0xffffffffu, v, src);
}

// C-fragment of a 16x16 fp32 matrix: CH[nn][4], nn = n-half (cols 8nn..8nn+7).
// Lane (g = lane>>2, t = lane&3):
//   CH[nn][0] = M[g  ][8nn+2t]   CH[nn][1] = M[g  ][8nn+2t+1]
//   CH[nn][2] = M[g+8][8nn+2t]   CH[nn][3] = M[g+8][8nn+2t+1]
// Element M[R][C]: lane (R&7)*4 + ((C&7)>>1), reg CH[C>>3][2*(R>>3)+(C&1)].

// C-frag -> col-major B-frags with tf32 hi/lo split.
__device__ __forceinline__ void conv_to_B(const float CH[2][4], int g, int t,
                                          uint32_t Bhi[2][2][2], uint32_t Blo[2][2][2]) {
    const int L  = 4 * t + (g >> 1);
    const int L2 = L + 16;
    const bool odd = (g & 1);
#pragma unroll
    for (int nn = 0; nn < 2; nn++)
#pragma unroll
        for (int kk = 0; kk < 2; kk++) {
            float e  = shfl(CH[nn][2 * kk],     L);
            float o  = shfl(CH[nn][2 * kk + 1], L);
            float b0 = odd ? o : e;
            float e2 = shfl(CH[nn][2 * kk],     L2);
            float o2 = shfl(CH[nn][2 * kk + 1], L2);
            float b1 = odd ? o2 : e2;
            split_tf32(b0, Bhi[kk][nn][0], Blo[kk][nn][0]);
            split_tf32(b1, Bhi[kk][nn][1], Blo[kk][nn][1]);
        }
}

// Register transpose: TH = C-frag layout of M^T given CH of M.
__device__ __forceinline__ void transpose_frag(const float CH[2][4], int g, int t,
                                               float TH[2][4]) {
    const int l0 = 8 * t + (g >> 1);
    const int l1 = l0 + 4;
    const bool odd = (g & 1);
#pragma unroll
    for (int nn = 0; nn < 2; nn++) {
        float e00 = shfl(CH[0][2 * nn],     l0);
        float o00 = shfl(CH[0][2 * nn + 1], l0);
        TH[nn][0] = odd ? o00 : e00;
        float e10 = shfl(CH[1][2 * nn],     l0);
        float o10 = shfl(CH[1][2 * nn + 1], l0);
        TH[nn][2] = odd ? o10 : e10;
        float e01 = shfl(CH[0][2 * nn],     l1);
        float o01 = shfl(CH[0][2 * nn + 1], l1);
        TH[nn][1] = odd ? o01 : e01;
        float e11 = shfl(CH[1][2 * nn],     l1);
        float o11 = shfl(CH[1][2 * nn + 1], l1);
        TH[nn][3] = odd ? o11 : e11;
    }
}

// Closed-form diag partial: lane holds diagonal elems iff t == g>>1;
// then they are CH[0][g&1] (row g) and CH[1][2+(g&1)] (row g+8).
__device__ __forceinline__ float diag_partial(const float CH[2][4], bool isdiag, bool godd) {
    float e0 = godd ? CH[0][1] : CH[0][0];
    float e1 = godd ? CH[1][3] : CH[1][2];
    return isdiag ? (e0 + e1) : 0.f;
}

__device__ __forceinline__ float frag_dot(const float A[2][4], const float B[2][4]) {
    float s = 0.f;
#pragma unroll
    for (int nn = 0; nn < 2; nn++)
#pragma unroll
        for (int r = 0; r < 4; r++) s = fmaf(A[nn][r], B[nn][r], s);
    return s;
}

__device__ __forceinline__ void mm_chain(const uint32_t Ahi[2][4], const uint32_t Alo[2][4],
                                         const uint32_t Bhi[2][2][2], const uint32_t Blo[2][2][2],
                                         float D[2][4]) {
#pragma unroll
    for (int nn = 0; nn < 2; nn++) {
        float d[4] = {0.f, 0.f, 0.f, 0.f};
#pragma unroll
        for (int kk = 0; kk < 2; kk++) {
            mma_tf32(d, Ahi[kk], Blo[kk][nn], d);
            mma_tf32(d, Alo[kk], Bhi[kk][nn], d);
            mma_tf32(d, Ahi[kk], Bhi[kk][nn], d);
        }
#pragma unroll
        for (int r = 0; r < 4; r++) D[nn][r] = d[r];
    }
}

__global__ void __launch_bounds__(128)
acoef_kernel(const float* __restrict__ x, const float* __restrict__ coef,
             float* __restrict__ out, int nsamples) {
    const int lane = threadIdx.x & 31;
    const int g = lane >> 2;
    const int t = lane & 3;
    const bool isdiag = (t == (g >> 1));
    const bool godd   = (g & 1);

    const long sample = (long)blockIdx.x * (blockDim.x >> 5) + (threadIdx.x >> 5);
    if (sample >= nsamples) return;
    const float* gx = x + sample * 256;

    // ---- load X fragments (A row-major, B col-major) with tf32 split ----
    uint32_t Ahi[2][4], Alo[2][4];
#pragma unroll
    for (int kk = 0; kk < 2; kk++) {
#pragma unroll
        for (int idx = 0; idx < 4; idx++) {
            int row = g + 8 * (idx & 1);
            int col = 8 * kk + t + 4 * (idx >> 1);
            float v = __ldg(gx + row * 16 + col);
            split_tf32(v, Ahi[kk][idx], Alo[kk][idx]);
        }
    }
    uint32_t Bhi[2][2][2], Blo[2][2][2];
#pragma unroll
    for (int kk = 0; kk < 2; kk++)
#pragma unroll
        for (int nn = 0; nn < 2; nn++) {
            float b0 = __ldg(gx + (8 * kk + t) * 16 + 8 * nn + g);
            float b1 = __ldg(gx + (8 * kk + t + 4) * 16 + 8 * nn + g);
            split_tf32(b0, Bhi[kk][nn][0], Blo[kk][nn][0]);
            split_tf32(b1, Bhi[kk][nn][1], Blo[kk][nn][1]);
        }

    float V[16];                    // trace partials; V[i] = tr(x^{i+2}), pad to 16
#pragma unroll
    for (int i = 10; i < 16; i++) V[i] = 0.f;

    float C2[2][4], C3[2][4], C4[2][4], C5[2][4], C6[2][4];
    float T4[2][4], T5[2][4];

    // mm1: x2 = X*X
    mm_chain(Ahi, Alo, Bhi, Blo, C2);
    V[0] = diag_partial(C2, isdiag, godd);          // tr2

    // mm2: x3 = X*x2
    conv_to_B(C2, g, t, Bhi, Blo);
    mm_chain(Ahi, Alo, Bhi, Blo, C3);
    V[1] = diag_partial(C3, isdiag, godd);          // tr3

    // mm3: x4 = X*x3
    conv_to_B(C3, g, t, Bhi, Blo);
    mm_chain(Ahi, Alo, Bhi, Blo, C4);
    V[2] = diag_partial(C4, isdiag, godd);          // tr4

    transpose_frag(C4, g, t, T4);
    V[5] = frag_dot(T4, C3);                        // tr7 = tr(x3*x4)
    V[6] = frag_dot(T4, C4);                        // tr8 = tr(x4*x4)

    // mm4: x5 = X*x4
    conv_to_B(C4, g, t, Bhi, Blo);
    mm_chain(Ahi, Alo, Bhi, Blo, C5);
    V[3] = diag_partial(C5, isdiag, godd);          // tr5
    V[7] = frag_dot(T4, C5);                        // tr9 = tr(x4*x5)

    transpose_frag(C5, g, t, T5);
    V[8] = frag_dot(T5, C5);                        // tr10 = tr(x5*x5)

    // mm5: x6 = X*x5
    conv_to_B(C5, g, t, Bhi, Blo);
    mm_chain(Ahi, Alo, Bhi, Blo, C6);
    V[4] = diag_partial(C6, isdiag, godd);          // tr6
    V[9] = frag_dot(T5, C6);                        // tr11 = tr(x5*x6)

    // ---- recursive-halving reduce-scatter over 32 lanes ----
    // After: lane L holds the full sum of trace index (L>>1)&15.
    {
        const bool h16 = (lane & 16);
#pragma unroll
        for (int k = 0; k < 8; k++) {
            float send = h16 ? V[k] : V[k + 8];
            float recv = __shfl_xor_sync(0xffffffffu, send, 16);
            V[k] = (h16 ? V[k + 8] : V[k]) + recv;
        }
        const bool h8 = (lane & 8);
#pragma unroll
        for (int k = 0; k < 4; k++) {
            float send = h8 ? V[k] : V[k + 4];
            float recv = __shfl_xor_sync(0xffffffffu, send, 8);
            V[k] = (h8 ? V[k + 4] : V[k]) + recv;
        }
        const bool h4 = (lane & 4);
#pragma unroll
        for (int k = 0; k < 2; k++) {
            float send = h4 ? V[k] : V[k + 2];
            float recv = __shfl_xor_sync(0xffffffffu, send, 4);
            V[k] = (h4 ? V[k + 2] : V[k]) + recv;
        }
        {
            const bool h2 = (lane & 2);
            float send = h2 ? V[0] : V[1];
            float recv = __shfl_xor_sync(0xffffffffu, send, 2);
            V[0] = (h2 ? V[1] : V[0]) + recv;
        }
        V[0] += __shfl_xor_sync(0xffffffffu, V[0], 1);
    }

    // ---- distributed polynomial: lane with trace i computes row i ----
    {
        const int i = (lane >> 1) & 15;
        const bool active = (lane < 20) && ((lane & 1) == 0);
        const int ic = (i < 10) ? i : 0;
        const float4 cf = __ldg((const float4*)coef + ic);
        const float u  = V[0] * (1.0f / 256.0f);
        const float u2 = u * u;
        float term = cf.x * u + cf.y * u2 + cf.z * (u2 * u) + cf.w * (u2 * u2);
        term *= __uint_as_float((uint32_t)(127 - 8 * i) << 23);   // 256^{-i}
        term = active ? term : 0.f;
#pragma unroll
        for (int off = 16; off >= 1; off >>= 1)
            term += __shfl_xor_sync(0xffffffffu, term, off);
        if (lane == 0) out[sample] = term;
    }
}

extern "C" void kernel_launch(void* const* d_in, const int* in_sizes, int n_in,
                              void* d_out, int out_size) {
    const float* x;
    const float* coef;
    if (n_in >= 2 && in_sizes[0] == 40) {
        coef = (const float*)d_in[0];
        x    = (const float*)d_in[1];
    } else {
        x    = (const float*)d_in[0];
        coef = (const float*)d_in[1];
    }
    float* out = (float*)d_out;
    int nsamples = out_size;
    const int warps_per_cta = 4;
    int grid = (nsamples + warps_per_cta - 1) / warps_per_cta;
    acoef_kernel<<<grid, warps_per_cta * 32>>>(x, coef, out, nsamples);
}

// round 7
// speedup vs baseline: 4.2661x; 1.0401x over previous
#include <cuda_runtime.h>
#include <cstdint>

// ACoef: per-sample traces of x^2..x^11 for 65536 16x16 fp32 matrices,
// out[b] = sum_{i,j} coef[i][j] * tr_{i+2}^(j+1) / 256^(i+j+1).
//
// One sample per WARP, tensor-core mma m16n8k8 tf32 with 3xTF32 compensation.
// Chain x2..x6 with A = X fixed; cross traces via register transposes + dots.
// R7: pre-staged single-shfl fragment conversions (8 shfl/conv, was 16),
// exploiting disjoint source-lane halves + parity-paired outputs.
// Reductions: recursive-halving reduce-scatter + distributed polynomial
// (redux.f32 is NOT supported on sm_103 -- verified ptxas error R6).

__device__ __forceinline__ void split_tf32(float v, uint32_t& hi, uint32_t& lo) {
    // hi = top 19 bits (tf32); lo = exact residual. mma ignores low 13 bits.
    hi = __float_as_uint(v) & 0xFFFFE000u;
    lo = __float_as_uint(v - __uint_as_float(hi));
}
__device__ __forceinline__ void mma_tf32(float d[4], const uint32_t a[4],
                                         const uint32_t b[2], const float c[4]) {
    asm volatile(
        "mma.sync.aligned.m16n8k8.row.col.f32.tf32.tf32.f32 "
        "{%0,%1,%2,%3}, {%4,%5,%6,%7}, {%8,%9}, {%10,%11,%12,%13};"
        : "=f"(d[0]), "=f"(d[1]), "=f"(d[2]), "=f"(d[3])
        : "r"(a[0]), "r"(a[1]), "r"(a[2]), "r"(a[3]),
          "r"(b[0]), "r"(b[1]),
          "f"(c[0]), "f"(c[1]), "f"(c[2]), "f"(c[3]));
}
__device__ __forceinline__ float shfl(float v, int src) {
    return __shfl_sync(0xffffffffu, v, src);
}

// C-fragment of a 16x16 fp32 matrix: CH[nn][4], nn = n-half (cols 8nn..8nn+7).
// Lane (g = lane>>2, t = lane&3):
//   CH[nn][0] = M[g  ][8nn+2t]   CH[nn][1] = M[g  ][8nn+2t+1]
//   CH[nn][2] = M[g+8][8nn+2t]   CH[nn][3] = M[g+8][8nn+2t+1]
// Element M[R][C]: lane (R&7)*4 + ((C&7)>>1), reg CH[C>>3][2*(R>>3)+(C&1)].

// C-frag -> col-major B-frags (tf32 hi/lo). Pre-staged single-shfl scheme:
//  b0 = M[8kk+t][8nn+g]   source lane 4t+(g>>1)      (lanes 0..15)
//  b1 = M[8kk+t+4][8nn+g] source lane 16+4t+(g>>1)   (lanes 16..31)
//  source reg CH[nn][2kk + (g&1)] in both cases.
// S1 stages CH[2kk] in lo-half lanes / CH[2kk+1] in hi-half; all lanes pull
// idxA = 4t+(g>>1)+16*(g&1): even-g receive b0, odd-g receive b1.
// S2 stages the complement; pull idxB = idxA^16: even-g get b1, odd-g get b0.
__device__ __forceinline__ void conv_to_B(const float CH[2][4], int idxA, int idxB,
                                          bool godd, bool hi16,
                                          uint32_t Bhi[2][2][2], uint32_t Blo[2][2][2]) {
#pragma unroll
    for (int nn = 0; nn < 2; nn++)
#pragma unroll
        for (int kk = 0; kk < 2; kk++) {
            float z1 = hi16 ? CH[nn][2 * kk + 1] : CH[nn][2 * kk];
            float s1 = shfl(z1, idxA);
            float z2 = hi16 ? CH[nn][2 * kk] : CH[nn][2 * kk + 1];
            float s2 = shfl(z2, idxB);
            float b0 = godd ? s2 : s1;
            float b1 = godd ? s1 : s2;
            split_tf32(b0, Bhi[kk][nn][0], Blo[kk][nn][0]);
            split_tf32(b1, Bhi[kk][nn][1], Blo[kk][nn][1]);
        }
}

// Register transpose, same pre-staged scheme.
//  TH[nn][2h+0] = M[8nn+2t][g+8h]   source lane 8t+(g>>1)    (lane&4 == 0)
//  TH[nn][2h+1] = M[8nn+2t+1][g+8h] source lane 8t+4+(g>>1)  (lane&4 != 0)
//  source reg CH[h][2nn + (g&1)].
__device__ __forceinline__ void transpose_frag(const float CH[2][4], int idxA, int idxB,
                                               bool godd, float TH[2][4]) {
#pragma unroll
    for (int nn = 0; nn < 2; nn++)
#pragma unroll
        for (int h = 0; h < 2; h++) {
            float z1 = godd ? CH[h][2 * nn + 1] : CH[h][2 * nn];
            float s1 = shfl(z1, idxA);
            float z2 = godd ? CH[h][2 * nn] : CH[h][2 * nn + 1];
            float s2 = shfl(z2, idxB);
            TH[nn][2 * h + 0] = godd ? s2 : s1;
            TH[nn][2 * h + 1] = godd ? s1 : s2;
        }
}

// Closed-form diag partial: lane holds diagonal elems iff t == g>>1;
// then they are CH[0][g&1] (row g) and CH[1][2+(g&1)] (row g+8).
__device__ __forceinline__ float diag_partial(const float CH[2][4], bool isdiag, bool godd) {
    float e0 = godd ? CH[0][1] : CH[0][0];
    float e1 = godd ? CH[1][3] : CH[1][2];
    return isdiag ? (e0 + e1) : 0.f;
}

__device__ __forceinline__ float frag_dot(const float A[2][4], const float B[2][4]) {
    float s = 0.f;
#pragma unroll
    for (int nn = 0; nn < 2; nn++)
#pragma unroll
        for (int r = 0; r < 4; r++) s = fmaf(A[nn][r], B[nn][r], s);
    return s;
}

__device__ __forceinline__ void mm_chain(const uint32_t Ahi[2][4], const uint32_t Alo[2][4],
                                         const uint32_t Bhi[2][2][2], const uint32_t Blo[2][2][2],
                                         float D[2][4]) {
#pragma unroll
    for (int nn = 0; nn < 2; nn++) {
        float d[4] = {0.f, 0.f, 0.f, 0.f};
#pragma unroll
        for (int kk = 0; kk < 2; kk++) {
            mma_tf32(d, Ahi[kk], Blo[kk][nn], d);
            mma_tf32(d, Alo[kk], Bhi[kk][nn], d);
            mma_tf32(d, Ahi[kk], Bhi[kk][nn], d);
        }
#pragma unroll
        for (int r = 0; r < 4; r++) D[nn][r] = d[r];
    }
}

__global__ void __launch_bounds__(128)
acoef_kernel(const float* __restrict__ x, const float* __restrict__ coef,
             float* __restrict__ out, int nsamples) {
    const int lane = threadIdx.x & 31;
    const int g = lane >> 2;
    const int t = lane & 3;
    const int q = g >> 1;
    const bool godd = (g & 1);
    const bool hi16 = (lane & 16);
    const bool isdiag = (t == q);

    // pre-staged shfl indices
    const int idxA_c = 4 * t + q + (godd ? 16 : 0);   // conv
    const int idxB_c = idxA_c ^ 16;
    const int idxA_t = 8 * t + q + (godd ? 4 : 0);    // transpose
    const int idxB_t = idxA_t ^ 4;

    const long sample = (long)blockIdx.x * (blockDim.x >> 5) + (threadIdx.x >> 5);
    if (sample >= nsamples) return;
    const float* gx = x + sample * 256;

    // ---- load X fragments (A row-major, B col-major) with tf32 split ----
    uint32_t Ahi[2][4], Alo[2][4];
#pragma unroll
    for (int kk = 0; kk < 2; kk++) {
#pragma unroll
        for (int idx = 0; idx < 4; idx++) {
            int row = g + 8 * (idx & 1);
            int col = 8 * kk + t + 4 * (idx >> 1);
            float v = __ldg(gx + row * 16 + col);
            split_tf32(v, Ahi[kk][idx], Alo[kk][idx]);
        }
    }
    uint32_t Bhi[2][2][2], Blo[2][2][2];
#pragma unroll
    for (int kk = 0; kk < 2; kk++)
#pragma unroll
        for (int nn = 0; nn < 2; nn++) {
            float b0 = __ldg(gx + (8 * kk + t) * 16 + 8 * nn + g);
            float b1 = __ldg(gx + (8 * kk + t + 4) * 16 + 8 * nn + g);
            split_tf32(b0, Bhi[kk][nn][0], Blo[kk][nn][0]);
            split_tf32(b1, Bhi[kk][nn][1], Blo[kk][nn][1]);
        }

    float V[16];   // trace partials; V[i] = partial of tr(x^{i+2}), pad to 16
#pragma unroll
    for (int i = 10; i < 16; i++) V[i] = 0.f;

    float C2[2][4], C3[2][4], C4[2][4], C5[2][4], C6[2][4];
    float T4[2][4], T5[2][4];

    // mm1: x2 = X*X
    mm_chain(Ahi, Alo, Bhi, Blo, C2);
    V[0] = diag_partial(C2, isdiag, godd);          // tr2

    // mm2: x3 = X*x2
    conv_to_B(C2, idxA_c, idxB_c, godd, hi16, Bhi, Blo);
    mm_chain(Ahi, Alo, Bhi, Blo, C3);
    V[1] = diag_partial(C3, isdiag, godd);          // tr3

    // mm3: x4 = X*x3
    conv_to_B(C3, idxA_c, idxB_c, godd, hi16, Bhi, Blo);
    mm_chain(Ahi, Alo, Bhi, Blo, C4);
    V[2] = diag_partial(C4, isdiag, godd);          // tr4

    transpose_frag(C4, idxA_t, idxB_t, godd, T4);
    V[5] = frag_dot(T4, C3);                        // tr7 = tr(x3*x4)
    V[6] = frag_dot(T4, C4);                        // tr8 = tr(x4*x4)

    // mm4: x5 = X*x4
    conv_to_B(C4, idxA_c, idxB_c, godd, hi16, Bhi, Blo);
    mm_chain(Ahi, Alo, Bhi, Blo, C5);
    V[3] = diag_partial(C5, isdiag, godd);          // tr5
    V[7] = frag_dot(T4, C5);                        // tr9 = tr(x4*x5)

    transpose_frag(C5, idxA_t, idxB_t, godd, T5);
    V[8] = frag_dot(T5, C5);                        // tr10 = tr(x5*x5)

    // mm5: x6 = X*x5
    conv_to_B(C5, idxA_c, idxB_c, godd, hi16, Bhi, Blo);
    mm_chain(Ahi, Alo, Bhi, Blo, C6);
    V[4] = diag_partial(C6, isdiag, godd);          // tr6
    V[9] = frag_dot(T5, C6);                        // tr11 = tr(x5*x6)

    // ---- recursive-halving reduce-scatter over 32 lanes ----
    // After: lane L holds the full sum of trace index (L>>1)&15.
    {
        const bool h16b = (lane & 16);
#pragma unroll
        for (int k = 0; k < 8; k++) {
            float send = h16b ? V[k] : V[k + 8];
            float recv = __shfl_xor_sync(0xffffffffu, send, 16);
            V[k] = (h16b ? V[k + 8] : V[k]) + recv;
        }
        const bool h8 = (lane & 8);
#pragma unroll
        for (int k = 0; k < 4; k++) {
            float send = h8 ? V[k] : V[k + 4];
            float recv = __shfl_xor_sync(0xffffffffu, send, 8);
            V[k] = (h8 ? V[k + 4] : V[k]) + recv;
        }
        const bool h4 = (lane & 4);
#pragma unroll
        for (int k = 0; k < 2; k++) {
            float send = h4 ? V[k] : V[k + 2];
            float recv = __shfl_xor_sync(0xffffffffu, send, 4);
            V[k] = (h4 ? V[k + 2] : V[k]) + recv;
        }
        {
            const bool h2 = (lane & 2);
            float send = h2 ? V[0] : V[1];
            float recv = __shfl_xor_sync(0xffffffffu, send, 2);
            V[0] = (h2 ? V[1] : V[0]) + recv;
        }
        V[0] += __shfl_xor_sync(0xffffffffu, V[0], 1);
    }

    // ---- distributed polynomial: lane holding trace i computes row i ----
    {
        const int i = (lane >> 1) & 15;
        const bool active = (lane < 20) && ((lane & 1) == 0);
        const int ic = (i < 10) ? i : 0;
        const float4 cf = __ldg((const float4*)coef + ic);
        const float u  = V[0] * (1.0f / 256.0f);
        const float u2 = u * u;
        float term = cf.x * u + cf.y * u2 + cf.z * (u2 * u) + cf.w * (u2 * u2);
        term *= __uint_as_float((uint32_t)(127 - 8 * i) << 23);   // 256^{-i}
        term = active ? term : 0.f;
#pragma unroll
        for (int off = 16; off >= 1; off >>= 1)
            term += __shfl_xor_sync(0xffffffffu, term, off);
        if (lane == 0) out[sample] = term;
    }
}

extern "C" void kernel_launch(void* const* d_in, const int* in_sizes, int n_in,
                              void* d_out, int out_size) {
    const float* x;
    const float* coef;
    if (n_in >= 2 && in_sizes[0] == 40) {
        coef = (const float*)d_in[0];
        x    = (const float*)d_in[1];
    } else {
        x    = (const float*)d_in[0];
        coef = (const float*)d_in[1];
    }
    float* out = (float*)d_out;
    int nsamples = out_size;
    const int warps_per_cta = 4;
    int grid = (nsamples + warps_per_cta - 1) / warps_per_cta;
    acoef_kernel<<<grid, warps_per_cta * 32>>>(x, coef, out, nsamples);
}

// round 8
// speedup vs baseline: 4.6068x; 1.0799x over previous
#include <cuda_runtime.h>
#include <cstdint>

// ACoef: per-sample traces of x^2..x^11 for 65536 16x16 fp32 matrices,
// out[b] = sum_{i,j} coef[i][j] * tr_{i+2}^(j+1) / 256^(i+j+1).
//
// One sample per WARP, tensor-core mma m16n8k8 tf32, 3xTF32 compensation.
// R8: 4-matmul addition chain x2=X*X, x3=X*x2, x5=x3*x2, x6=x3*x3 (24 mma,
// was 30). A-fragment of x3 obtained FREE from transpose T3: A-frag(M) ==
// B-frag(M^T) with register renaming. Traces: tr2,tr3 = diagonals; the rest
// are elementwise frag dots <Tp, Cq> over transposes T2, T3, T5.

__device__ __forceinline__ void split_tf32(float v, uint32_t& hi, uint32_t& lo) {
    hi = __float_as_uint(v) & 0xFFFFE000u;
    lo = __float_as_uint(v - __uint_as_float(hi));
}
__device__ __forceinline__ void mma_tf32(float d[4], const uint32_t a[4],
                                         const uint32_t b[2], const float c[4]) {
    asm volatile(
        "mma.sync.aligned.m16n8k8.row.col.f32.tf32.tf32.f32 "
        "{%0,%1,%2,%3}, {%4,%5,%6,%7}, {%8,%9}, {%10,%11,%12,%13};"
        : "=f"(d[0]), "=f"(d[1]), "=f"(d[2]), "=f"(d[3])
        : "r"(a[0]), "r"(a[1]), "r"(a[2]), "r"(a[3]),
          "r"(b[0]), "r"(b[1]),
          "f"(c[0]), "f"(c[1]), "f"(c[2]), "f"(c[3]));
}
__device__ __forceinline__ float shfl(float v, int src) {
    return __shfl_sync(0xffffffffu, v, src);
}

// C-fragment of a 16x16 fp32 matrix: CH[nn][4], nn = n-half (cols 8nn..8nn+7).
// Lane (g = lane>>2, t = lane&3):
//   CH[nn][0] = M[g  ][8nn+2t]   CH[nn][1] = M[g  ][8nn+2t+1]
//   CH[nn][2] = M[g+8][8nn+2t]   CH[nn][3] = M[g+8][8nn+2t+1]
// Element M[R][C]: lane (R&7)*4 + ((C&7)>>1), reg CH[C>>3][2*(R>>3)+(C&1)].

// C-frag -> col-major B-frags (tf32 hi/lo), pre-staged single-shfl scheme.
//  b0 = M[8kk+t][8nn+g], b1 = M[8kk+t+4][8nn+g].
__device__ __forceinline__ void conv_to_B(const float CH[2][4], int idxA, int idxB,
                                          bool godd, bool hi16,
                                          uint32_t Bhi[2][2][2], uint32_t Blo[2][2][2]) {
#pragma unroll
    for (int nn = 0; nn < 2; nn++)
#pragma unroll
        for (int kk = 0; kk < 2; kk++) {
            float z1 = hi16 ? CH[nn][2 * kk + 1] : CH[nn][2 * kk];
            float s1 = shfl(z1, idxA);
            float z2 = hi16 ? CH[nn][2 * kk] : CH[nn][2 * kk + 1];
            float s2 = shfl(z2, idxB);
            float b0 = godd ? s2 : s1;
            float b1 = godd ? s1 : s2;
            split_tf32(b0, Bhi[kk][nn][0], Blo[kk][nn][0]);
            split_tf32(b1, Bhi[kk][nn][1], Blo[kk][nn][1]);
        }
}

// Register transpose: TH = C-frag layout of M^T given CH of M (pre-staged).
__device__ __forceinline__ void transpose_frag(const float CH[2][4], int idxA, int idxB,
                                               bool godd, float TH[2][4]) {
#pragma unroll
    for (int nn = 0; nn < 2; nn++)
#pragma unroll
        for (int h = 0; h < 2; h++) {
            float z1 = godd ? CH[h][2 * nn + 1] : CH[h][2 * nn];
            float s1 = shfl(z1, idxA);
            float z2 = godd ? CH[h][2 * nn] : CH[h][2 * nn + 1];
            float s2 = shfl(z2, idxB);
            TH[nn][2 * h + 0] = godd ? s2 : s1;
            TH[nn][2 * h + 1] = godd ? s1 : s2;
        }
}

// Closed-form diag partial: lane holds diagonal elems iff t == g>>1.
__device__ __forceinline__ float diag_partial(const float CH[2][4], bool isdiag, bool godd) {
    float e0 = godd ? CH[0][1] : CH[0][0];
    float e1 = godd ? CH[1][3] : CH[1][2];
    return isdiag ? (e0 + e1) : 0.f;
}

// <A, B> over fragment positions; frag_dot(T_p, C_q) = tr(x^p * x^q).
__device__ __forceinline__ float frag_dot(const float A[2][4], const float B[2][4]) {
    float s = 0.f;
#pragma unroll
    for (int nn = 0; nn < 2; nn++)
#pragma unroll
        for (int r = 0; r < 4; r++) s = fmaf(A[nn][r], B[nn][r], s);
    return s;
}

__device__ __forceinline__ void mm_chain(const uint32_t Ahi[2][4], const uint32_t Alo[2][4],
                                         const uint32_t Bhi[2][2][2], const uint32_t Blo[2][2][2],
                                         float D[2][4]) {
#pragma unroll
    for (int nn = 0; nn < 2; nn++) {
        float d[4] = {0.f, 0.f, 0.f, 0.f};
#pragma unroll
        for (int kk = 0; kk < 2; kk++) {
            mma_tf32(d, Ahi[kk], Blo[kk][nn], d);
            mma_tf32(d, Alo[kk], Bhi[kk][nn], d);
            mma_tf32(d, Ahi[kk], Bhi[kk][nn], d);
        }
#pragma unroll
        for (int r = 0; r < 4; r++) D[nn][r] = d[r];
    }
}

__global__ void __launch_bounds__(128)
acoef_kernel(const float* __restrict__ x, const float* __restrict__ coef,
             float* __restrict__ out, int nsamples) {
    const int lane = threadIdx.x & 31;
    const int g = lane >> 2;
    const int t = lane & 3;
    const int q = g >> 1;
    const bool godd = (g & 1);
    const bool hi16 = (lane & 16);
    const bool isdiag = (t == q);

    const int idxA_c = 4 * t + q + (godd ? 16 : 0);   // conv
    const int idxB_c = idxA_c ^ 16;
    const int idxA_t = 8 * t + q + (godd ? 4 : 0);    // transpose
    const int idxB_t = idxA_t ^ 4;

    const long sample = (long)blockIdx.x * (blockDim.x >> 5) + (threadIdx.x >> 5);
    if (sample >= nsamples) return;
    const float* gx = x + sample * 256;

    // ---- load X fragments: A row-major + B col-major, tf32 split ----
    uint32_t AXhi[2][4], AXlo[2][4];
#pragma unroll
    for (int kk = 0; kk < 2; kk++) {
#pragma unroll
        for (int idx = 0; idx < 4; idx++) {
            int row = g + 8 * (idx & 1);
            int col = 8 * kk + t + 4 * (idx >> 1);
            float v = __ldg(gx + row * 16 + col);
            split_tf32(v, AXhi[kk][idx], AXlo[kk][idx]);
        }
    }
    uint32_t BXhi[2][2][2], BXlo[2][2][2];
#pragma unroll
    for (int kk = 0; kk < 2; kk++)
#pragma unroll
        for (int nn = 0; nn < 2; nn++) {
            float b0 = __ldg(gx + (8 * kk + t) * 16 + 8 * nn + g);
            float b1 = __ldg(gx + (8 * kk + t + 4) * 16 + 8 * nn + g);
            split_tf32(b0, BXhi[kk][nn][0], BXlo[kk][nn][0]);
            split_tf32(b1, BXhi[kk][nn][1], BXlo[kk][nn][1]);
        }

    float V[16];   // V[i] = partial of tr(x^{i+2}); pad to 16 for reduce-scatter
#pragma unroll
    for (int i = 10; i < 16; i++) V[i] = 0.f;

    float C2[2][4], C3[2][4], C5[2][4], C6[2][4];
    float T2[2][4], T3[2][4], T5[2][4];

    // mm1: x2 = X*X
    mm_chain(AXhi, AXlo, BXhi, BXlo, C2);
    V[0] = diag_partial(C2, isdiag, godd);          // tr2

    // B(x2) + T2; tr4 = <T2, C2>; C2 dead after
    uint32_t Bc2hi[2][2][2], Bc2lo[2][2][2];
    conv_to_B(C2, idxA_c, idxB_c, godd, hi16, Bc2hi, Bc2lo);
    transpose_frag(C2, idxA_t, idxB_t, godd, T2);
    V[2] = frag_dot(T2, C2);                        // tr4

    // mm2: x3 = X*x2   (A(X) dead after)
    mm_chain(AXhi, AXlo, Bc2hi, Bc2lo, C3);
    V[1] = diag_partial(C3, isdiag, godd);          // tr3
    V[3] = frag_dot(T2, C3);                        // tr5 = tr(x2*x3)

    // T3; tr6 = <T3, C3>; A(x3) = conv(T3) (A-frag(M) == B-frag(M^T))
    transpose_frag(C3, idxA_t, idxB_t, godd, T3);
    V[4] = frag_dot(T3, C3);                        // tr6 = tr(x3*x3)

    uint32_t Bt3hi[2][2][2], Bt3lo[2][2][2];
    conv_to_B(T3, idxA_c, idxB_c, godd, hi16, Bt3hi, Bt3lo);
    uint32_t A3hi[2][4], A3lo[2][4];
#pragma unroll
    for (int kk = 0; kk < 2; kk++) {
        A3hi[kk][0] = Bt3hi[kk][0][0]; A3hi[kk][1] = Bt3hi[kk][1][0];
        A3hi[kk][2] = Bt3hi[kk][0][1]; A3hi[kk][3] = Bt3hi[kk][1][1];
        A3lo[kk][0] = Bt3lo[kk][0][0]; A3lo[kk][1] = Bt3lo[kk][1][0];
        A3lo[kk][2] = Bt3lo[kk][0][1]; A3lo[kk][3] = Bt3lo[kk][1][1];
    }

    // mm3: x5 = x3*x2   (Bc2 dead after)
    mm_chain(A3hi, A3lo, Bc2hi, Bc2lo, C5);
    V[5] = frag_dot(T2, C5);                        // tr7 = tr(x2*x5); T2 dead
    V[6] = frag_dot(T3, C5);                        // tr8 = tr(x3*x5)

    // B(x3) deferred until here (C3 kept live instead of 16-reg Bc3)
    uint32_t Bc3hi[2][2][2], Bc3lo[2][2][2];
    conv_to_B(C3, idxA_c, idxB_c, godd, hi16, Bc3hi, Bc3lo);

    // mm4: x6 = x3*x3   (A3, Bc3 dead after)
    mm_chain(A3hi, A3lo, Bc3hi, Bc3lo, C6);

    transpose_frag(C5, idxA_t, idxB_t, godd, T5);
    V[8] = frag_dot(T5, C5);                        // tr10 = tr(x5*x5)
    V[7] = frag_dot(T3, C6);                        // tr9  = tr(x3*x6); T3 dead
    V[9] = frag_dot(T5, C6);                        // tr11 = tr(x5*x6)

    // ---- recursive-halving reduce-scatter over 32 lanes ----
    // After: lane L holds the full sum of trace index (L>>1)&15.
    {
        const bool h16b = (lane & 16);
#pragma unroll
        for (int k = 0; k < 8; k++) {
            float send = h16b ? V[k] : V[k + 8];
            float recv = __shfl_xor_sync(0xffffffffu, send, 16);
            V[k] = (h16b ? V[k + 8] : V[k]) + recv;
        }
        const bool h8 = (lane & 8);
#pragma unroll
        for (int k = 0; k < 4; k++) {
            float send = h8 ? V[k] : V[k + 4];
            float recv = __shfl_xor_sync(0xffffffffu, send, 8);
            V[k] = (h8 ? V[k + 4] : V[k]) + recv;
        }
        const bool h4 = (lane & 4);
#pragma unroll
        for (int k = 0; k < 2; k++) {
            float send = h4 ? V[k] : V[k + 2];
            float recv = __shfl_xor_sync(0xffffffffu, send, 4);
            V[k] = (h4 ? V[k + 2] : V[k]) + recv;
        }
        {
            const bool h2 = (lane & 2);
            float send = h2 ? V[0] : V[1];
            float recv = __shfl_xor_sync(0xffffffffu, send, 2);
            V[0] = (h2 ? V[1] : V[0]) + recv;
        }
        V[0] += __shfl_xor_sync(0xffffffffu, V[0], 1);
    }

    // ---- distributed polynomial: lane holding trace i computes row i ----
    {
        const int i = (lane >> 1) & 15;
        const bool active = (lane < 20) && ((lane & 1) == 0);
        const int ic = (i < 10) ? i : 0;
        const float4 cf = __ldg((const float4*)coef + ic);
        const float u  = V[0] * (1.0f / 256.0f);
        const float u2 = u * u;
        float term = cf.x * u + cf.y * u2 + cf.z * (u2 * u) + cf.w * (u2 * u2);
        term *= __uint_as_float((uint32_t)(127 - 8 * i) << 23);   // 256^{-i}
        term = active ? term : 0.f;
#pragma unroll
        for (int off = 16; off >= 1; off >>= 1)
            term += __shfl_xor_sync(0xffffffffu, term, off);
        if (lane == 0) out[sample] = term;
    }
}

extern "C" void kernel_launch(void* const* d_in, const int* in_sizes, int n_in,
                              void* d_out, int out_size) {
    const float* x;
    const float* coef;
    if (n_in >= 2 && in_sizes[0] == 40) {
        coef = (const float*)d_in[0];
        x    = (const float*)d_in[1];
    } else {
        x    = (const float*)d_in[0];
        coef = (const float*)d_in[1];
    }
    float* out = (float*)d_out;
    int nsamples = out_size;
    const int warps_per_cta = 4;
    int grid = (nsamples + warps_per_cta - 1) / warps_per_cta;
    acoef_kernel<<<grid, warps_per_cta * 32>>>(x, coef, out, nsamples);
}